// round 14
// baseline (speedup 1.0000x reference)
#include <cuda_runtime.h>
#include <cuda_bf16.h>
#include <math.h>
#include <cstdint>

#define BATCH   2
#define S_LEN   2048
#define HDIM    2048
#define HK      16
#define HV      32
#define DK      128
#define DV      128
#define KEY_DIM   (HK*DK)
#define VAL_DIM   (HV*DV)
#define QKVZ_COLS (2*KEY_DIM + 2*VAL_DIM)
#define NTOK    (BATCH*S_LEN)
#define EPSV    1e-6f

// ---------------- scratch ----------------
__device__ float g_qkvz [ (size_t)NTOK * QKVZ_COLS ];
__device__ float g_ba   [ (size_t)NTOK * 64 ];
__device__ float g_q    [ (size_t)NTOK * KEY_DIM ];
__device__ float g_k    [ (size_t)NTOK * KEY_DIM ];
__device__ float g_v    [ (size_t)NTOK * VAL_DIM ];
__device__ float g_decay[ (size_t)NTOK * HV ];
__device__ float g_beta [ (size_t)NTOK * HV ];
__device__ float g_core [ (size_t)NTOK * VAL_DIM ];
__device__ __align__(256) __nv_bfloat16 g_Ahi [ (size_t)NTOK * HDIM ];
__device__ __align__(256) __nv_bfloat16 g_Alo [ (size_t)NTOK * HDIM ];
__device__ __align__(256) __nv_bfloat16 g_B1hi[ (size_t)QKVZ_COLS * HDIM ];
__device__ __align__(256) __nv_bfloat16 g_B1lo[ (size_t)QKVZ_COLS * HDIM ];
__device__ __align__(256) __nv_bfloat16 g_WOhi[ (size_t)HDIM * VAL_DIM ];
__device__ __align__(256) __nv_bfloat16 g_WOlo[ (size_t)HDIM * VAL_DIM ];
__device__ __align__(256) __nv_bfloat16 g_Yhi [ (size_t)NTOK * VAL_DIM ];
__device__ __align__(256) __nv_bfloat16 g_Ylo [ (size_t)NTOK * VAL_DIM ];

// ---------------- helpers ----------------
__device__ __forceinline__ float2 ffma2(float2 a, float2 b, float2 c) {
    float2 d;
    asm("fma.rn.f32x2 %0, %1, %2, %3;"
        : "=l"(reinterpret_cast<unsigned long long&>(d))
        : "l"(reinterpret_cast<unsigned long long&>(a)),
          "l"(reinterpret_cast<unsigned long long&>(b)),
          "l"(reinterpret_cast<unsigned long long&>(c)));
    return d;
}
__device__ __forceinline__ float2 fmul2(float2 a, float2 b) {
    float2 d;
    asm("mul.rn.f32x2 %0, %1, %2;"
        : "=l"(reinterpret_cast<unsigned long long&>(d))
        : "l"(reinterpret_cast<unsigned long long&>(a)),
          "l"(reinterpret_cast<unsigned long long&>(b)));
    return d;
}
__device__ __forceinline__ uint32_t smem_u32f(const void* p) {
    uint32_t a;
    asm("{ .reg .u64 t; cvta.to.shared.u64 t, %1; cvt.u32.u64 %0, t; }" : "=r"(a) : "l"(p));
    return a;
}
__device__ __forceinline__ void cp16(uint32_t s, const void* g) {
    asm volatile("cp.async.cg.shared.global [%0], [%1], 16;" :: "r"(s), "l"(g));
}
__device__ __forceinline__ void ldsm4(uint32_t& r0, uint32_t& r1, uint32_t& r2,
                                      uint32_t& r3, uint32_t a) {
    asm volatile("ldmatrix.sync.aligned.m8n8.x4.shared.b16 {%0,%1,%2,%3}, [%4];"
        : "=r"(r0), "=r"(r1), "=r"(r2), "=r"(r3) : "r"(a));
}
__device__ __forceinline__ void mma16816(float* c, const uint32_t* a, const uint32_t* b) {
    asm volatile("mma.sync.aligned.m16n8k16.row.col.f32.bf16.bf16.f32 "
        "{%0,%1,%2,%3}, {%4,%5,%6,%7}, {%8,%9}, {%0,%1,%2,%3};"
        : "+f"(c[0]), "+f"(c[1]), "+f"(c[2]), "+f"(c[3])
        : "r"(a[0]), "r"(a[1]), "r"(a[2]), "r"(a[3]), "r"(b[0]), "r"(b[1]));
}

// ---------------------------------------------------------------------------
// bf16 split GEMM via mma.sync (baseline PTX, works on .target sm_103):
//   C[M,N] fp32 = (Ahi+Alo)[M,K] @ (Bhi+Blo)[N,K]^T
// 3 passes (hi*hi, hi*lo, lo*hi) accumulated in registers.
// CTA 128x128, BK=64 bf16 (128B SW128 rows), 3-stage cp.async, 256 threads.
// Warp grid 2(M)x4(N), warp tile 64x32. grid = (M/128, N/128).
// ---------------------------------------------------------------------------
#define STAGES 3
#define GMM_SMEM (STAGES * 32768)   // 96 KB

__global__ __launch_bounds__(256, 2)
void gemm_mma_kernel(const __nv_bfloat16* __restrict__ Ahi,
                     const __nv_bfloat16* __restrict__ Alo,
                     const __nv_bfloat16* __restrict__ Bhi,
                     const __nv_bfloat16* __restrict__ Blo,
                     float* __restrict__ C, int Nn, int Kdim)
{
    extern __shared__ char smem[];
    const uint32_t sb = smem_u32f(smem);
    const int tid  = threadIdx.x;
    const int wid  = tid >> 5;
    const int lane = tid & 31;
    const int m0   = blockIdx.x * 128;
    const int n0   = blockIdx.y * 128;
    const int wm   = (wid & 1) * 64;
    const int wn   = (wid >> 1) * 32;
    const int kseg = Kdim >> 6;
    const int nst  = 3 * kseg;

    float acc[4][4][4];
#pragma unroll
    for (int i = 0; i < 4; i++)
#pragma unroll
        for (int j = 0; j < 4; j++)
#pragma unroll
            for (int q = 0; q < 4; q++) acc[i][j][q] = 0.f;

    // ldmatrix per-thread constants
    const int arow  = wm + (lane & 15);
    const int aksel = lane >> 4;                                // 0/1 (16B chunk)
    const int brow  = wn + ((lane >> 4) << 3) + (lane & 7);
    const int bksel = (lane >> 3) & 1;
    const int x7a = arow & 7, x7b = brow & 7;
    uint32_t a_base[4], b_base[2];
#pragma unroll
    for (int fm = 0; fm < 4; fm++) a_base[fm] = (uint32_t)(arow + fm * 16) * 128u;
#pragma unroll
    for (int j = 0; j < 2; j++)    b_base[j]  = (uint32_t)(brow + j * 16) * 128u;

    auto load_stage = [&](int gs, int st) {
        int pass = gs / kseg;
        int kk   = gs - pass * kseg;
        const __nv_bfloat16* As = (pass < 2)  ? Ahi : Alo;
        const __nv_bfloat16* Bs = (pass == 1) ? Blo : Bhi;
        const char* ag = (const char*)As + ((size_t)m0 * Kdim + (size_t)kk * 64) * 2;
        const char* bg = (const char*)Bs + ((size_t)n0 * Kdim + (size_t)kk * 64) * 2;
        uint32_t ab = sb + st * 16384;
        uint32_t bb = sb + STAGES * 16384 + st * 16384;
#pragma unroll
        for (int i = 0; i < 4; i++) {
            int it  = tid + (i << 8);               // 0..1023
            int row = it >> 3, ch = it & 7;
            uint32_t so = (uint32_t)row * 128u + (uint32_t)((ch ^ (row & 7)) << 4);
            const size_t go = (size_t)row * Kdim * 2 + (size_t)ch * 16;
            cp16(ab + so, ag + go);
            cp16(bb + so, bg + go);
        }
    };

    load_stage(0, 0);
    asm volatile("cp.async.commit_group;" ::: "memory");
    load_stage(1, 1);
    asm volatile("cp.async.commit_group;" ::: "memory");

    for (int gs = 0; gs < nst; ++gs) {
        const int st = gs % STAGES;
        asm volatile("cp.async.wait_group 1;" ::: "memory");
        __syncthreads();
        if (gs + 2 < nst) load_stage(gs + 2, (gs + 2) % STAGES);
        asm volatile("cp.async.commit_group;" ::: "memory");

        const uint32_t ab = sb + st * 16384;
        const uint32_t bb = sb + STAGES * 16384 + st * 16384;
#pragma unroll
        for (int k16 = 0; k16 < 4; k16++) {
            uint32_t a[4][4], b[2][4];
            const int cha = k16 * 2 + aksel;
            const int chb = k16 * 2 + bksel;
#pragma unroll
            for (int fm = 0; fm < 4; fm++)
                ldsm4(a[fm][0], a[fm][1], a[fm][2], a[fm][3],
                      ab + a_base[fm] + (uint32_t)((cha ^ x7a) << 4));
#pragma unroll
            for (int j = 0; j < 2; j++)
                ldsm4(b[j][0], b[j][1], b[j][2], b[j][3],
                      bb + b_base[j] + (uint32_t)((chb ^ x7b) << 4));
#pragma unroll
            for (int fm = 0; fm < 4; fm++)
#pragma unroll
                for (int fn = 0; fn < 4; fn++)
                    mma16816(acc[fm][fn], a[fm], &b[fn >> 1][(fn & 1) * 2]);
        }
    }

    // epilogue: c-frag lane L -> rows (L/4, L/4+8), cols 2*(L%4)..+1
    const int rowb = m0 + wm + (lane >> 2);
    const int colb = n0 + wn + ((lane & 3) << 1);
#pragma unroll
    for (int fm = 0; fm < 4; fm++)
#pragma unroll
        for (int fn = 0; fn < 4; fn++) {
            int r = rowb + fm * 16, c = colb + fn * 8;
            *reinterpret_cast<float2*>(&C[(size_t)r * Nn + c]) =
                make_float2(acc[fm][fn][0], acc[fm][fn][1]);
            *reinterpret_cast<float2*>(&C[(size_t)(r + 8) * Nn + c]) =
                make_float2(acc[fm][fn][2], acc[fm][fn][3]);
        }
}

// ---------------- fp32 -> bf16 hi/lo split ----------------
__global__ __launch_bounds__(256)
void convert_split_kernel(const float* __restrict__ X, __nv_bfloat16* __restrict__ hi,
                          __nv_bfloat16* __restrict__ lo, size_t n)
{
    size_t i = ((size_t)blockIdx.x * blockDim.x + threadIdx.x) * 4;
    if (i >= n) return;
    float4 v = *reinterpret_cast<const float4*>(X + i);
    float vv[4] = {v.x, v.y, v.z, v.w};
    unsigned short h[4], l[4];
#pragma unroll
    for (int j = 0; j < 4; j++) {
        __nv_bfloat16 hb = __float2bfloat16(vv[j]);
        __nv_bfloat16 lb = __float2bfloat16(vv[j] - __bfloat162float(hb));
        h[j] = *(unsigned short*)&hb; l[j] = *(unsigned short*)&lb;
    }
    *reinterpret_cast<ushort4*>(hi + i) = make_ushort4(h[0], h[1], h[2], h[3]);
    *reinterpret_cast<ushort4*>(lo + i) = make_ushort4(l[0], l[1], l[2], l[3]);
}

// ---------------- transpose + split: W[R,Cn] fp32 -> [Cn,R] bf16 ----------------
__global__ __launch_bounds__(256)
void transconv_kernel(const float* __restrict__ W, __nv_bfloat16* __restrict__ hi,
                      __nv_bfloat16* __restrict__ lo, int R, int Cn)
{
    __shared__ float t[32][33];
    const int bx = blockIdx.x * 32, by = blockIdx.y * 32;
    const int tx = threadIdx.x & 31, ty = threadIdx.x >> 5;
#pragma unroll
    for (int i = 0; i < 4; i++)
        t[ty + 8 * i][tx] = W[(size_t)(by + ty + 8 * i) * Cn + bx + tx];
    __syncthreads();
#pragma unroll
    for (int i = 0; i < 4; i++) {
        float v = t[tx][ty + 8 * i];
        __nv_bfloat16 h = __float2bfloat16(v);
        size_t off = (size_t)(bx + ty + 8 * i) * R + by + tx;
        hi[off] = h;
        lo[off] = __float2bfloat16(v - __bfloat162float(h));
    }
}

// ---------------- small fp32 SGEMM (ba only) ----------------
__global__ __launch_bounds__(256, 2)
void sgemm_kernel(const float* __restrict__ A, const float* __restrict__ B,
                  float* __restrict__ C, int M, int N, int K)
{
    __shared__ __align__(16) float As[16][128];
    __shared__ __align__(16) float Bs[16][128];
    const int tid = threadIdx.x;
    const int tx  = tid & 15, ty = tid >> 4;
    const int m0  = blockIdx.y * 128, n0 = blockIdx.x * 128;
    float2 cc[8][4];
#pragma unroll
    for (int i = 0; i < 8; i++)
#pragma unroll
        for (int j = 0; j < 4; j++) cc[i][j] = make_float2(0.f, 0.f);
    for (int k0 = 0; k0 < K; k0 += 16) {
#pragma unroll
        for (int q = 0; q < 2; q++) {
            int it = q * 256 + tid, ar = it >> 2, ac = (it & 3) * 4;
            float4 va = *reinterpret_cast<const float4*>(&A[(size_t)(m0 + ar) * K + k0 + ac]);
            As[ac+0][ar] = va.x; As[ac+1][ar] = va.y; As[ac+2][ar] = va.z; As[ac+3][ar] = va.w;
        }
#pragma unroll
        for (int q = 0; q < 2; q++) {
            int it = q * 256 + tid, br = it >> 5, bc = (it & 31) * 4;
            float4 vb = make_float4(0.f, 0.f, 0.f, 0.f);
            if (n0 + bc < N)
                vb = *reinterpret_cast<const float4*>(&B[(size_t)(k0 + br) * N + n0 + bc]);
            *reinterpret_cast<float4*>(&Bs[br][bc]) = vb;
        }
        __syncthreads();
#pragma unroll
        for (int kk = 0; kk < 16; kk++) {
            float4 a0 = *reinterpret_cast<const float4*>(&As[kk][ty * 8]);
            float4 a1 = *reinterpret_cast<const float4*>(&As[kk][ty * 8 + 4]);
            float4 b0 = *reinterpret_cast<const float4*>(&Bs[kk][tx * 8]);
            float4 b1 = *reinterpret_cast<const float4*>(&Bs[kk][tx * 8 + 4]);
            float  aa[8] = {a0.x, a0.y, a0.z, a0.w, a1.x, a1.y, a1.z, a1.w};
            float2 bb[4] = { make_float2(b0.x, b0.y), make_float2(b0.z, b0.w),
                             make_float2(b1.x, b1.y), make_float2(b1.z, b1.w) };
#pragma unroll
            for (int i = 0; i < 8; i++) {
                float2 a2 = make_float2(aa[i], aa[i]);
#pragma unroll
                for (int j = 0; j < 4; j++) cc[i][j] = ffma2(a2, bb[j], cc[i][j]);
            }
        }
        __syncthreads();
    }
#pragma unroll
    for (int i = 0; i < 8; i++) {
        size_t row = (size_t)(m0 + ty * 8 + i) * N;
        int col = n0 + tx * 8;
        if (col < N)
            *reinterpret_cast<float4*>(&C[row + col]) =
                make_float4(cc[i][0].x, cc[i][0].y, cc[i][1].x, cc[i][1].y);
        if (col + 4 < N)
            *reinterpret_cast<float4*>(&C[row + col + 4]) =
                make_float4(cc[i][2].x, cc[i][2].y, cc[i][3].x, cc[i][3].y);
    }
}

// ---------------- conv + silu + l2norm + gates ----------------
__global__ __launch_bounds__(512)
void conv_kernel(const float* __restrict__ qkvz, const float* __restrict__ ba,
                 const float* __restrict__ conv_w, const float* __restrict__ A_log,
                 const float* __restrict__ dt_bias,
                 float* __restrict__ qo, float* __restrict__ ko,
                 float* __restrict__ vo, float* __restrict__ decay,
                 float* __restrict__ beta)
{
    const int bs   = blockIdx.x;
    const int s    = bs & (S_LEN - 1);
    const int tid  = threadIdx.x;
    const int warp = tid >> 5, lane = tid & 31;

    if (tid < 32) {
        int hv = tid;
        float bg = ba[(size_t)bs * 64 + (hv >> 1) * 4 + (hv & 1)];
        float ag = ba[(size_t)bs * 64 + (hv >> 1) * 4 + 2 + (hv & 1)];
        float x  = ag + dt_bias[hv];
        float sp = (x > 20.f) ? x : log1pf(expf(x));
        decay[(size_t)bs * HV + hv] = expf(-expf(A_log[hv]) * sp);
        beta [(size_t)bs * HV + hv] = 1.f / (1.f + expf(-bg));
    }

    for (int g = warp; g < 64; g += 16) {
        float vals[4];
        float sumsq = 0.f;
#pragma unroll
        for (int i = 0; i < 4; i++) {
            int d = lane + 32 * i;
            int col;
            if (g < 16)       col = g * 768 + d;
            else if (g < 32)  col = (g - 16) * 768 + 128 + d;
            else              col = ((g - 32) >> 1) * 768 + 256 + ((g - 32) & 1) * 128 + d;
            float4 w4 = *reinterpret_cast<const float4*>(&conv_w[(size_t)(g * 128 + d) * 4]);
            float wj[4] = {w4.x, w4.y, w4.z, w4.w};
            float acc = 0.f;
#pragma unroll
            for (int j = 0; j < 4; j++) {
                int sj = s - 3 + j;
                if (sj >= 0)
                    acc += qkvz[(size_t)(bs - 3 + j) * QKVZ_COLS + col] * wj[j];
            }
            float sv = acc / (1.f + expf(-acc));
            vals[i] = sv;
            sumsq += sv * sv;
        }
        if (g < 32) {
#pragma unroll
            for (int off = 16; off; off >>= 1)
                sumsq += __shfl_xor_sync(0xffffffffu, sumsq, off);
            float rn = rsqrtf(sumsq + EPSV);
            float* dst = (g < 16) ? &qo[((size_t)bs * HK + g) * DK]
                                  : &ko[((size_t)bs * HK + (g - 16)) * DK];
#pragma unroll
            for (int i = 0; i < 4; i++) dst[lane + 32 * i] = vals[i] * rn;
        } else {
            float* dst = &vo[((size_t)bs * HV + (g - 32)) * DV];
#pragma unroll
            for (int i = 0; i < 4; i++) dst[lane + 32 * i] = vals[i];
        }
    }
}

// ---------------- delta-rule scan ----------------
__global__ __launch_bounds__(256)
void scan_kernel(const float* __restrict__ qo, const float* __restrict__ ko,
                 const float* __restrict__ vo, const float* __restrict__ decay,
                 const float* __restrict__ beta, float* __restrict__ core)
{
    const int blk = blockIdx.x;
    const int b = blk >> 6, h = (blk >> 1) & 31, vh = blk & 1, hq = h >> 1;
    const int tid = threadIdx.x, p = tid >> 6, vl = tid & 63;

    __shared__ __align__(16) float sh_q[128];
    __shared__ __align__(16) float sh_k[128];
    __shared__ __align__(16) float sh_v[64];
    __shared__ float red_kv[256];
    __shared__ float red_o[256];
    __shared__ float sh_scal[2];

    const float scale = 0.088388347648318447f;
    float2 Sst[16];
#pragma unroll
    for (int j = 0; j < 16; j++) Sst[j] = make_float2(0.f, 0.f);

    const float* qp = qo + ((size_t)b * S_LEN * HK + hq) * DK;
    const float* kp = ko + ((size_t)b * S_LEN * HK + hq) * DK;
    const float* vp = vo + ((size_t)b * S_LEN * HV + h) * DV + vh * 64;
    const float* dp = decay + (size_t)b * S_LEN * HV + h;
    const float* bp = beta  + (size_t)b * S_LEN * HV + h;
    float* op = core + ((size_t)b * S_LEN * HV + h) * DV + vh * 64;

    float pq = 0.f, pk = 0.f, pv = 0.f, pd = 0.f, pb = 0.f;
    if (tid < 128) { pq = qp[tid]; pk = kp[tid]; }
    if (tid < 64)  { pv = vp[tid]; }
    if (tid == 0)  { pd = dp[0]; pb = bp[0]; }

    for (int t = 0; t < S_LEN; ++t) {
        __syncthreads();
        if (t > 0 && p == 0) {
            float o = red_o[vl] + red_o[64 + vl] + red_o[128 + vl] + red_o[192 + vl];
            op[(size_t)(t - 1) * VAL_DIM + vl] = o * scale;
        }
        if (tid < 128) { sh_q[tid] = pq; sh_k[tid] = pk; }
        if (tid < 64)  { sh_v[tid] = pv; }
        if (tid == 0)  { sh_scal[0] = pd; sh_scal[1] = pb; }
        if (t + 1 < S_LEN) {
            if (tid < 128) {
                pq = qp[(size_t)(t + 1) * KEY_DIM + tid];
                pk = kp[(size_t)(t + 1) * KEY_DIM + tid];
            }
            if (tid < 64)  pv = vp[(size_t)(t + 1) * VAL_DIM + tid];
            if (tid == 0)  { pd = dp[(size_t)(t + 1) * HV]; pb = bp[(size_t)(t + 1) * HV]; }
        }
        __syncthreads();

        const float2* k2 = reinterpret_cast<const float2*>(sh_k + p * 32);
        float2 acc = make_float2(0.f, 0.f);
#pragma unroll
        for (int j = 0; j < 16; j++) acc = ffma2(k2[j], Sst[j], acc);
        red_kv[p * 64 + vl] = acc.x + acc.y;
        __syncthreads();

        float dec = sh_scal[0], bet = sh_scal[1];
        float kv = dec * (red_kv[vl] + red_kv[64 + vl] + red_kv[128 + vl] + red_kv[192 + vl]);
        float u  = bet * (sh_v[vl] - kv);
        float2 u2 = make_float2(u, u);
        float2 d2 = make_float2(dec, dec);
        const float2* q2 = reinterpret_cast<const float2*>(sh_q + p * 32);
        float2 oacc = make_float2(0.f, 0.f);
#pragma unroll
        for (int j = 0; j < 16; j++) {
            Sst[j] = ffma2(Sst[j], d2, fmul2(k2[j], u2));
            oacc   = ffma2(q2[j], Sst[j], oacc);
        }
        red_o[p * 64 + vl] = oacc.x + oacc.y;
    }
    __syncthreads();
    if (p == 0) {
        float o = red_o[vl] + red_o[64 + vl] + red_o[128 + vl] + red_o[192 + vl];
        op[(size_t)(S_LEN - 1) * VAL_DIM + vl] = o * scale;
    }
}

// ---------------- gated RMSNorm -> bf16 hi/lo of y ----------------
__global__ __launch_bounds__(1024)
void post_kernel(const float* __restrict__ core, const float* __restrict__ qkvz,
                 const float* __restrict__ norm_w,
                 __nv_bfloat16* __restrict__ Yhi, __nv_bfloat16* __restrict__ Ylo)
{
    const int bs = blockIdx.x;
    const int warp = threadIdx.x >> 5, lane = threadIdx.x & 31;

    const float* cp = core + ((size_t)bs * HV + warp) * DV;
    const int zcol  = (warp >> 1) * 768 + 512 + (warp & 1) * 128;
    const float* zp = qkvz + (size_t)bs * QKVZ_COLS + zcol;

    float c[4]; float ss = 0.f;
#pragma unroll
    for (int i = 0; i < 4; i++) { c[i] = cp[lane + 32 * i]; ss += c[i] * c[i]; }
#pragma unroll
    for (int off = 16; off; off >>= 1) ss += __shfl_xor_sync(0xffffffffu, ss, off);
    float rn = rsqrtf(ss * (1.f / 128.f) + EPSV);

    size_t base = (size_t)bs * VAL_DIM + warp * DV;
#pragma unroll
    for (int i = 0; i < 4; i++) {
        int d = lane + 32 * i;
        float z  = zp[d];
        float yv = c[i] * rn * norm_w[d] * (z / (1.f + expf(-z)));
        __nv_bfloat16 h = __float2bfloat16(yv);
        Yhi[base + d] = h;
        Ylo[base + d] = __float2bfloat16(yv - __bfloat162float(h));
    }
}

// ---------------- launch ----------------
extern "C" void kernel_launch(void* const* d_in, const int* in_sizes, int n_in,
                              void* d_out, int out_size)
{
    const float* hs     = (const float*)d_in[0];
    const float* w_qkvz = (const float*)d_in[1];
    const float* w_ba   = (const float*)d_in[2];
    const float* conv_w = (const float*)d_in[3];
    const float* A_log  = (const float*)d_in[4];
    const float* dt_b   = (const float*)d_in[5];
    const float* norm_w = (const float*)d_in[6];
    const float* w_out  = (const float*)d_in[7];
    float* out = (float*)d_out;

    cudaFuncSetAttribute(gemm_mma_kernel,
                         cudaFuncAttributeMaxDynamicSharedMemorySize, GMM_SMEM);

    void *pv;
    cudaGetSymbolAddress(&pv, g_qkvz);  float* qkvz = (float*)pv;
    cudaGetSymbolAddress(&pv, g_ba);    float* ba   = (float*)pv;
    cudaGetSymbolAddress(&pv, g_q);     float* q    = (float*)pv;
    cudaGetSymbolAddress(&pv, g_k);     float* k    = (float*)pv;
    cudaGetSymbolAddress(&pv, g_v);     float* v    = (float*)pv;
    cudaGetSymbolAddress(&pv, g_decay); float* dec  = (float*)pv;
    cudaGetSymbolAddress(&pv, g_beta);  float* bet  = (float*)pv;
    cudaGetSymbolAddress(&pv, g_core);  float* core = (float*)pv;
    cudaGetSymbolAddress(&pv, g_Ahi);   __nv_bfloat16* Ahi  = (__nv_bfloat16*)pv;
    cudaGetSymbolAddress(&pv, g_Alo);   __nv_bfloat16* Alo  = (__nv_bfloat16*)pv;
    cudaGetSymbolAddress(&pv, g_B1hi);  __nv_bfloat16* B1hi = (__nv_bfloat16*)pv;
    cudaGetSymbolAddress(&pv, g_B1lo);  __nv_bfloat16* B1lo = (__nv_bfloat16*)pv;
    cudaGetSymbolAddress(&pv, g_WOhi);  __nv_bfloat16* WOhi = (__nv_bfloat16*)pv;
    cudaGetSymbolAddress(&pv, g_WOlo);  __nv_bfloat16* WOlo = (__nv_bfloat16*)pv;
    cudaGetSymbolAddress(&pv, g_Yhi);   __nv_bfloat16* Yhi  = (__nv_bfloat16*)pv;
    cudaGetSymbolAddress(&pv, g_Ylo);   __nv_bfloat16* Ylo  = (__nv_bfloat16*)pv;

    // operand prep
    {
        size_t n = (size_t)NTOK * HDIM;
        convert_split_kernel<<<(unsigned)((n / 4 + 255) / 256), 256>>>(hs, Ahi, Alo, n);
    }
    transconv_kernel<<<dim3(QKVZ_COLS / 32, HDIM / 32), 256>>>(w_qkvz, B1hi, B1lo, HDIM, QKVZ_COLS);
    transconv_kernel<<<dim3(HDIM / 32, VAL_DIM / 32), 256>>>(w_out, WOhi, WOlo, VAL_DIM, HDIM);

    // 1) qkvz = hs @ w_qkvz   (tensor cores, 3-pass bf16 split)
    gemm_mma_kernel<<<dim3(NTOK / 128, QKVZ_COLS / 128), 256, GMM_SMEM>>>(
        Ahi, Alo, B1hi, B1lo, qkvz, QKVZ_COLS, HDIM);

    // 2) ba = hs @ w_ba  (fp32)
    sgemm_kernel<<<dim3(1, NTOK / 128), 256>>>(hs, w_ba, ba, NTOK, 64, HDIM);

    // 3) conv + gates
    conv_kernel<<<NTOK, 512>>>(qkvz, ba, conv_w, A_log, dt_b, q, k, v, dec, bet);

    // 4) scan
    scan_kernel<<<BATCH * HV * 2, 256>>>(q, k, v, dec, bet, core);

    // 5) RMSNorm -> y (bf16 split)
    post_kernel<<<NTOK, 1024>>>(core, qkvz, norm_w, Yhi, Ylo);

    // 6) out = y @ w_out  (tensor cores, 3-pass bf16 split)
    gemm_mma_kernel<<<dim3(NTOK / 128, HDIM / 128), 256, GMM_SMEM>>>(
        Yhi, Ylo, WOhi, WOlo, out, HDIM, VAL_DIM);
}

// round 15
// speedup vs baseline: 1.0012x; 1.0012x over previous
#include <cuda_runtime.h>
#include <cuda_bf16.h>
#include <math.h>
#include <cstdint>

#define BATCH   2
#define S_LEN   2048
#define HDIM    2048
#define HK      16
#define HV      32
#define DK      128
#define DV      128
#define KEY_DIM   (HK*DK)
#define VAL_DIM   (HV*DV)
#define QKVZ_COLS (2*KEY_DIM + 2*VAL_DIM)
#define NTOK    (BATCH*S_LEN)
#define EPSV    1e-6f

// ---------------- scratch ----------------
__device__ float g_qkvz [ (size_t)NTOK * QKVZ_COLS ];
__device__ float g_ba   [ (size_t)NTOK * 64 ];
__device__ float g_q    [ (size_t)NTOK * KEY_DIM ];
__device__ float g_k    [ (size_t)NTOK * KEY_DIM ];
__device__ float g_v    [ (size_t)NTOK * VAL_DIM ];
__device__ float g_decay[ (size_t)NTOK * HV ];
__device__ float g_beta [ (size_t)NTOK * HV ];
__device__ float g_core [ (size_t)NTOK * VAL_DIM ];
__device__ __align__(256) __nv_bfloat16 g_Ahi [ (size_t)NTOK * HDIM ];
__device__ __align__(256) __nv_bfloat16 g_Alo [ (size_t)NTOK * HDIM ];
__device__ __align__(256) __nv_bfloat16 g_B1hi[ (size_t)QKVZ_COLS * HDIM ];
__device__ __align__(256) __nv_bfloat16 g_B1lo[ (size_t)QKVZ_COLS * HDIM ];
__device__ __align__(256) __nv_bfloat16 g_WOhi[ (size_t)HDIM * VAL_DIM ];
__device__ __align__(256) __nv_bfloat16 g_WOlo[ (size_t)HDIM * VAL_DIM ];
__device__ __align__(256) __nv_bfloat16 g_Yhi [ (size_t)NTOK * VAL_DIM ];
__device__ __align__(256) __nv_bfloat16 g_Ylo [ (size_t)NTOK * VAL_DIM ];

// ---------------- helpers ----------------
__device__ __forceinline__ float2 ffma2(float2 a, float2 b, float2 c) {
    float2 d;
    asm("fma.rn.f32x2 %0, %1, %2, %3;"
        : "=l"(reinterpret_cast<unsigned long long&>(d))
        : "l"(reinterpret_cast<unsigned long long&>(a)),
          "l"(reinterpret_cast<unsigned long long&>(b)),
          "l"(reinterpret_cast<unsigned long long&>(c)));
    return d;
}
__device__ __forceinline__ float2 fmul2(float2 a, float2 b) {
    float2 d;
    asm("mul.rn.f32x2 %0, %1, %2;"
        : "=l"(reinterpret_cast<unsigned long long&>(d))
        : "l"(reinterpret_cast<unsigned long long&>(a)),
          "l"(reinterpret_cast<unsigned long long&>(b)));
    return d;
}
__device__ __forceinline__ uint32_t smem_u32f(const void* p) {
    uint32_t a;
    asm("{ .reg .u64 t; cvta.to.shared.u64 t, %1; cvt.u32.u64 %0, t; }" : "=r"(a) : "l"(p));
    return a;
}
__device__ __forceinline__ void cp16(uint32_t s, const void* g) {
    asm volatile("cp.async.cg.shared.global [%0], [%1], 16;" :: "r"(s), "l"(g));
}
__device__ __forceinline__ void ldsm4(uint32_t& r0, uint32_t& r1, uint32_t& r2,
                                      uint32_t& r3, uint32_t a) {
    asm volatile("ldmatrix.sync.aligned.m8n8.x4.shared.b16 {%0,%1,%2,%3}, [%4];"
        : "=r"(r0), "=r"(r1), "=r"(r2), "=r"(r3) : "r"(a));
}
__device__ __forceinline__ void mma16816(float* c, const uint32_t* a, const uint32_t* b) {
    asm volatile("mma.sync.aligned.m16n8k16.row.col.f32.bf16.bf16.f32 "
        "{%0,%1,%2,%3}, {%4,%5,%6,%7}, {%8,%9}, {%0,%1,%2,%3};"
        : "+f"(c[0]), "+f"(c[1]), "+f"(c[2]), "+f"(c[3])
        : "r"(a[0]), "r"(a[1]), "r"(a[2]), "r"(a[3]), "r"(b[0]), "r"(b[1]));
}

// ---------------------------------------------------------------------------
// bf16 split GEMM via mma.sync (baseline PTX, works on .target sm_103):
//   C[M,N] fp32 = (Ahi+Alo)[M,K] @ (Bhi+Blo)[N,K]^T
// 3 passes (hi*hi, hi*lo, lo*hi) accumulated in registers.
// CTA 128x128, BK=64 bf16 (128B SW128 rows), 3-stage cp.async, 256 threads.
// Warp grid 2(M)x4(N), warp tile 64x32. grid = (M/128, N/128).
// ---------------------------------------------------------------------------
#define STAGES 3
#define GMM_SMEM (STAGES * 32768)   // 96 KB

__global__ __launch_bounds__(256, 2)
void gemm_mma_kernel(const __nv_bfloat16* __restrict__ Ahi,
                     const __nv_bfloat16* __restrict__ Alo,
                     const __nv_bfloat16* __restrict__ Bhi,
                     const __nv_bfloat16* __restrict__ Blo,
                     float* __restrict__ C, int Nn, int Kdim)
{
    extern __shared__ char smem[];
    const uint32_t sb = smem_u32f(smem);
    const int tid  = threadIdx.x;
    const int wid  = tid >> 5;
    const int lane = tid & 31;
    const int m0   = blockIdx.x * 128;
    const int n0   = blockIdx.y * 128;
    const int wm   = (wid & 1) * 64;
    const int wn   = (wid >> 1) * 32;
    const int kseg = Kdim >> 6;
    const int nst  = 3 * kseg;

    float acc[4][4][4];
#pragma unroll
    for (int i = 0; i < 4; i++)
#pragma unroll
        for (int j = 0; j < 4; j++)
#pragma unroll
            for (int q = 0; q < 4; q++) acc[i][j][q] = 0.f;

    // ldmatrix per-thread constants
    const int arow  = wm + (lane & 15);
    const int aksel = lane >> 4;                                // 0/1 (16B chunk)
    const int brow  = wn + ((lane >> 4) << 3) + (lane & 7);
    const int bksel = (lane >> 3) & 1;
    const int x7a = arow & 7, x7b = brow & 7;
    uint32_t a_base[4], b_base[2];
#pragma unroll
    for (int fm = 0; fm < 4; fm++) a_base[fm] = (uint32_t)(arow + fm * 16) * 128u;
#pragma unroll
    for (int j = 0; j < 2; j++)    b_base[j]  = (uint32_t)(brow + j * 16) * 128u;

    auto load_stage = [&](int gs, int st) {
        int pass = gs / kseg;
        int kk   = gs - pass * kseg;
        const __nv_bfloat16* As = (pass < 2)  ? Ahi : Alo;
        const __nv_bfloat16* Bs = (pass == 1) ? Blo : Bhi;
        const char* ag = (const char*)As + ((size_t)m0 * Kdim + (size_t)kk * 64) * 2;
        const char* bg = (const char*)Bs + ((size_t)n0 * Kdim + (size_t)kk * 64) * 2;
        uint32_t ab = sb + st * 16384;
        uint32_t bb = sb + STAGES * 16384 + st * 16384;
#pragma unroll
        for (int i = 0; i < 4; i++) {
            int it  = tid + (i << 8);               // 0..1023
            int row = it >> 3, ch = it & 7;
            uint32_t so = (uint32_t)row * 128u + (uint32_t)((ch ^ (row & 7)) << 4);
            const size_t go = (size_t)row * Kdim * 2 + (size_t)ch * 16;
            cp16(ab + so, ag + go);
            cp16(bb + so, bg + go);
        }
    };

    load_stage(0, 0);
    asm volatile("cp.async.commit_group;" ::: "memory");
    load_stage(1, 1);
    asm volatile("cp.async.commit_group;" ::: "memory");

    for (int gs = 0; gs < nst; ++gs) {
        const int st = gs % STAGES;
        asm volatile("cp.async.wait_group 1;" ::: "memory");
        __syncthreads();
        if (gs + 2 < nst) load_stage(gs + 2, (gs + 2) % STAGES);
        asm volatile("cp.async.commit_group;" ::: "memory");

        const uint32_t ab = sb + st * 16384;
        const uint32_t bb = sb + STAGES * 16384 + st * 16384;
#pragma unroll
        for (int k16 = 0; k16 < 4; k16++) {
            uint32_t a[4][4], b[2][4];
            const int cha = k16 * 2 + aksel;
            const int chb = k16 * 2 + bksel;
#pragma unroll
            for (int fm = 0; fm < 4; fm++)
                ldsm4(a[fm][0], a[fm][1], a[fm][2], a[fm][3],
                      ab + a_base[fm] + (uint32_t)((cha ^ x7a) << 4));
#pragma unroll
            for (int j = 0; j < 2; j++)
                ldsm4(b[j][0], b[j][1], b[j][2], b[j][3],
                      bb + b_base[j] + (uint32_t)((chb ^ x7b) << 4));
#pragma unroll
            for (int fm = 0; fm < 4; fm++)
#pragma unroll
                for (int fn = 0; fn < 4; fn++)
                    mma16816(acc[fm][fn], a[fm], &b[fn >> 1][(fn & 1) * 2]);
        }
    }

    // epilogue: c-frag lane L -> rows (L/4, L/4+8), cols 2*(L%4)..+1
    const int rowb = m0 + wm + (lane >> 2);
    const int colb = n0 + wn + ((lane & 3) << 1);
#pragma unroll
    for (int fm = 0; fm < 4; fm++)
#pragma unroll
        for (int fn = 0; fn < 4; fn++) {
            int r = rowb + fm * 16, c = colb + fn * 8;
            *reinterpret_cast<float2*>(&C[(size_t)r * Nn + c]) =
                make_float2(acc[fm][fn][0], acc[fm][fn][1]);
            *reinterpret_cast<float2*>(&C[(size_t)(r + 8) * Nn + c]) =
                make_float2(acc[fm][fn][2], acc[fm][fn][3]);
        }
}

// ---------------- fp32 -> bf16 hi/lo split ----------------
__global__ __launch_bounds__(256)
void convert_split_kernel(const float* __restrict__ X, __nv_bfloat16* __restrict__ hi,
                          __nv_bfloat16* __restrict__ lo, size_t n)
{
    size_t i = ((size_t)blockIdx.x * blockDim.x + threadIdx.x) * 4;
    if (i >= n) return;
    float4 v = *reinterpret_cast<const float4*>(X + i);
    float vv[4] = {v.x, v.y, v.z, v.w};
    unsigned short h[4], l[4];
#pragma unroll
    for (int j = 0; j < 4; j++) {
        __nv_bfloat16 hb = __float2bfloat16(vv[j]);
        __nv_bfloat16 lb = __float2bfloat16(vv[j] - __bfloat162float(hb));
        h[j] = *(unsigned short*)&hb; l[j] = *(unsigned short*)&lb;
    }
    *reinterpret_cast<ushort4*>(hi + i) = make_ushort4(h[0], h[1], h[2], h[3]);
    *reinterpret_cast<ushort4*>(lo + i) = make_ushort4(l[0], l[1], l[2], l[3]);
}

// ---------------- transpose + split: W[R,Cn] fp32 -> [Cn,R] bf16 ----------------
__global__ __launch_bounds__(256)
void transconv_kernel(const float* __restrict__ W, __nv_bfloat16* __restrict__ hi,
                      __nv_bfloat16* __restrict__ lo, int R, int Cn)
{
    __shared__ float t[32][33];
    const int bx = blockIdx.x * 32, by = blockIdx.y * 32;
    const int tx = threadIdx.x & 31, ty = threadIdx.x >> 5;
#pragma unroll
    for (int i = 0; i < 4; i++)
        t[ty + 8 * i][tx] = W[(size_t)(by + ty + 8 * i) * Cn + bx + tx];
    __syncthreads();
#pragma unroll
    for (int i = 0; i < 4; i++) {
        float v = t[tx][ty + 8 * i];
        __nv_bfloat16 h = __float2bfloat16(v);
        size_t off = (size_t)(bx + ty + 8 * i) * R + by + tx;
        hi[off] = h;
        lo[off] = __float2bfloat16(v - __bfloat162float(h));
    }
}

// ---------------- small fp32 SGEMM (ba only) ----------------
__global__ __launch_bounds__(256, 2)
void sgemm_kernel(const float* __restrict__ A, const float* __restrict__ B,
                  float* __restrict__ C, int M, int N, int K)
{
    __shared__ __align__(16) float As[16][128];
    __shared__ __align__(16) float Bs[16][128];
    const int tid = threadIdx.x;
    const int tx  = tid & 15, ty = tid >> 4;
    const int m0  = blockIdx.y * 128, n0 = blockIdx.x * 128;
    float2 cc[8][4];
#pragma unroll
    for (int i = 0; i < 8; i++)
#pragma unroll
        for (int j = 0; j < 4; j++) cc[i][j] = make_float2(0.f, 0.f);
    for (int k0 = 0; k0 < K; k0 += 16) {
#pragma unroll
        for (int q = 0; q < 2; q++) {
            int it = q * 256 + tid, ar = it >> 2, ac = (it & 3) * 4;
            float4 va = *reinterpret_cast<const float4*>(&A[(size_t)(m0 + ar) * K + k0 + ac]);
            As[ac+0][ar] = va.x; As[ac+1][ar] = va.y; As[ac+2][ar] = va.z; As[ac+3][ar] = va.w;
        }
#pragma unroll
        for (int q = 0; q < 2; q++) {
            int it = q * 256 + tid, br = it >> 5, bc = (it & 31) * 4;
            float4 vb = make_float4(0.f, 0.f, 0.f, 0.f);
            if (n0 + bc < N)
                vb = *reinterpret_cast<const float4*>(&B[(size_t)(k0 + br) * N + n0 + bc]);
            *reinterpret_cast<float4*>(&Bs[br][bc]) = vb;
        }
        __syncthreads();
#pragma unroll
        for (int kk = 0; kk < 16; kk++) {
            float4 a0 = *reinterpret_cast<const float4*>(&As[kk][ty * 8]);
            float4 a1 = *reinterpret_cast<const float4*>(&As[kk][ty * 8 + 4]);
            float4 b0 = *reinterpret_cast<const float4*>(&Bs[kk][tx * 8]);
            float4 b1 = *reinterpret_cast<const float4*>(&Bs[kk][tx * 8 + 4]);
            float  aa[8] = {a0.x, a0.y, a0.z, a0.w, a1.x, a1.y, a1.z, a1.w};
            float2 bb[4] = { make_float2(b0.x, b0.y), make_float2(b0.z, b0.w),
                             make_float2(b1.x, b1.y), make_float2(b1.z, b1.w) };
#pragma unroll
            for (int i = 0; i < 8; i++) {
                float2 a2 = make_float2(aa[i], aa[i]);
#pragma unroll
                for (int j = 0; j < 4; j++) cc[i][j] = ffma2(a2, bb[j], cc[i][j]);
            }
        }
        __syncthreads();
    }
#pragma unroll
    for (int i = 0; i < 8; i++) {
        size_t row = (size_t)(m0 + ty * 8 + i) * N;
        int col = n0 + tx * 8;
        if (col < N)
            *reinterpret_cast<float4*>(&C[row + col]) =
                make_float4(cc[i][0].x, cc[i][0].y, cc[i][1].x, cc[i][1].y);
        if (col + 4 < N)
            *reinterpret_cast<float4*>(&C[row + col + 4]) =
                make_float4(cc[i][2].x, cc[i][2].y, cc[i][3].x, cc[i][3].y);
    }
}

// ---------------- conv + silu + l2norm + gates ----------------
__global__ __launch_bounds__(512)
void conv_kernel(const float* __restrict__ qkvz, const float* __restrict__ ba,
                 const float* __restrict__ conv_w, const float* __restrict__ A_log,
                 const float* __restrict__ dt_bias,
                 float* __restrict__ qo, float* __restrict__ ko,
                 float* __restrict__ vo, float* __restrict__ decay,
                 float* __restrict__ beta)
{
    const int bs   = blockIdx.x;
    const int s    = bs & (S_LEN - 1);
    const int tid  = threadIdx.x;
    const int warp = tid >> 5, lane = tid & 31;

    if (tid < 32) {
        int hv = tid;
        float bg = ba[(size_t)bs * 64 + (hv >> 1) * 4 + (hv & 1)];
        float ag = ba[(size_t)bs * 64 + (hv >> 1) * 4 + 2 + (hv & 1)];
        float x  = ag + dt_bias[hv];
        float sp = (x > 20.f) ? x : log1pf(expf(x));
        decay[(size_t)bs * HV + hv] = expf(-expf(A_log[hv]) * sp);
        beta [(size_t)bs * HV + hv] = 1.f / (1.f + expf(-bg));
    }

    for (int g = warp; g < 64; g += 16) {
        float vals[4];
        float sumsq = 0.f;
#pragma unroll
        for (int i = 0; i < 4; i++) {
            int d = lane + 32 * i;
            int col;
            if (g < 16)       col = g * 768 + d;
            else if (g < 32)  col = (g - 16) * 768 + 128 + d;
            else              col = ((g - 32) >> 1) * 768 + 256 + ((g - 32) & 1) * 128 + d;
            float4 w4 = *reinterpret_cast<const float4*>(&conv_w[(size_t)(g * 128 + d) * 4]);
            float wj[4] = {w4.x, w4.y, w4.z, w4.w};
            float acc = 0.f;
#pragma unroll
            for (int j = 0; j < 4; j++) {
                int sj = s - 3 + j;
                if (sj >= 0)
                    acc += qkvz[(size_t)(bs - 3 + j) * QKVZ_COLS + col] * wj[j];
            }
            float sv = acc / (1.f + expf(-acc));
            vals[i] = sv;
            sumsq += sv * sv;
        }
        if (g < 32) {
#pragma unroll
            for (int off = 16; off; off >>= 1)
                sumsq += __shfl_xor_sync(0xffffffffu, sumsq, off);
            float rn = rsqrtf(sumsq + EPSV);
            float* dst = (g < 16) ? &qo[((size_t)bs * HK + g) * DK]
                                  : &ko[((size_t)bs * HK + (g - 16)) * DK];
#pragma unroll
            for (int i = 0; i < 4; i++) dst[lane + 32 * i] = vals[i] * rn;
        } else {
            float* dst = &vo[((size_t)bs * HV + (g - 32)) * DV];
#pragma unroll
            for (int i = 0; i < 4; i++) dst[lane + 32 * i] = vals[i];
        }
    }
}

// ---------------- delta-rule scan ----------------
__global__ __launch_bounds__(256)
void scan_kernel(const float* __restrict__ qo, const float* __restrict__ ko,
                 const float* __restrict__ vo, const float* __restrict__ decay,
                 const float* __restrict__ beta, float* __restrict__ core)
{
    const int blk = blockIdx.x;
    const int b = blk >> 6, h = (blk >> 1) & 31, vh = blk & 1, hq = h >> 1;
    const int tid = threadIdx.x, p = tid >> 6, vl = tid & 63;

    __shared__ __align__(16) float sh_q[128];
    __shared__ __align__(16) float sh_k[128];
    __shared__ __align__(16) float sh_v[64];
    __shared__ float red_kv[256];
    __shared__ float red_o[256];
    __shared__ float sh_scal[2];

    const float scale = 0.088388347648318447f;
    float2 Sst[16];
#pragma unroll
    for (int j = 0; j < 16; j++) Sst[j] = make_float2(0.f, 0.f);

    const float* qp = qo + ((size_t)b * S_LEN * HK + hq) * DK;
    const float* kp = ko + ((size_t)b * S_LEN * HK + hq) * DK;
    const float* vp = vo + ((size_t)b * S_LEN * HV + h) * DV + vh * 64;
    const float* dp = decay + (size_t)b * S_LEN * HV + h;
    const float* bp = beta  + (size_t)b * S_LEN * HV + h;
    float* op = core + ((size_t)b * S_LEN * HV + h) * DV + vh * 64;

    float pq = 0.f, pk = 0.f, pv = 0.f, pd = 0.f, pb = 0.f;
    if (tid < 128) { pq = qp[tid]; pk = kp[tid]; }
    if (tid < 64)  { pv = vp[tid]; }
    if (tid == 0)  { pd = dp[0]; pb = bp[0]; }

    for (int t = 0; t < S_LEN; ++t) {
        __syncthreads();
        if (t > 0 && p == 0) {
            float o = red_o[vl] + red_o[64 + vl] + red_o[128 + vl] + red_o[192 + vl];
            op[(size_t)(t - 1) * VAL_DIM + vl] = o * scale;
        }
        if (tid < 128) { sh_q[tid] = pq; sh_k[tid] = pk; }
        if (tid < 64)  { sh_v[tid] = pv; }
        if (tid == 0)  { sh_scal[0] = pd; sh_scal[1] = pb; }
        if (t + 1 < S_LEN) {
            if (tid < 128) {
                pq = qp[(size_t)(t + 1) * KEY_DIM + tid];
                pk = kp[(size_t)(t + 1) * KEY_DIM + tid];
            }
            if (tid < 64)  pv = vp[(size_t)(t + 1) * VAL_DIM + tid];
            if (tid == 0)  { pd = dp[(size_t)(t + 1) * HV]; pb = bp[(size_t)(t + 1) * HV]; }
        }
        __syncthreads();

        const float2* k2 = reinterpret_cast<const float2*>(sh_k + p * 32);
        float2 acc = make_float2(0.f, 0.f);
#pragma unroll
        for (int j = 0; j < 16; j++) acc = ffma2(k2[j], Sst[j], acc);
        red_kv[p * 64 + vl] = acc.x + acc.y;
        __syncthreads();

        float dec = sh_scal[0], bet = sh_scal[1];
        float kv = dec * (red_kv[vl] + red_kv[64 + vl] + red_kv[128 + vl] + red_kv[192 + vl]);
        float u  = bet * (sh_v[vl] - kv);
        float2 u2 = make_float2(u, u);
        float2 d2 = make_float2(dec, dec);
        const float2* q2 = reinterpret_cast<const float2*>(sh_q + p * 32);
        float2 oacc = make_float2(0.f, 0.f);
#pragma unroll
        for (int j = 0; j < 16; j++) {
            Sst[j] = ffma2(Sst[j], d2, fmul2(k2[j], u2));
            oacc   = ffma2(q2[j], Sst[j], oacc);
        }
        red_o[p * 64 + vl] = oacc.x + oacc.y;
    }
    __syncthreads();
    if (p == 0) {
        float o = red_o[vl] + red_o[64 + vl] + red_o[128 + vl] + red_o[192 + vl];
        op[(size_t)(S_LEN - 1) * VAL_DIM + vl] = o * scale;
    }
}

// ---------------- gated RMSNorm -> bf16 hi/lo of y ----------------
__global__ __launch_bounds__(1024)
void post_kernel(const float* __restrict__ core, const float* __restrict__ qkvz,
                 const float* __restrict__ norm_w,
                 __nv_bfloat16* __restrict__ Yhi, __nv_bfloat16* __restrict__ Ylo)
{
    const int bs = blockIdx.x;
    const int warp = threadIdx.x >> 5, lane = threadIdx.x & 31;

    const float* cp = core + ((size_t)bs * HV + warp) * DV;
    const int zcol  = (warp >> 1) * 768 + 512 + (warp & 1) * 128;
    const float* zp = qkvz + (size_t)bs * QKVZ_COLS + zcol;

    float c[4]; float ss = 0.f;
#pragma unroll
    for (int i = 0; i < 4; i++) { c[i] = cp[lane + 32 * i]; ss += c[i] * c[i]; }
#pragma unroll
    for (int off = 16; off; off >>= 1) ss += __shfl_xor_sync(0xffffffffu, ss, off);
    float rn = rsqrtf(ss * (1.f / 128.f) + EPSV);

    size_t base = (size_t)bs * VAL_DIM + warp * DV;
#pragma unroll
    for (int i = 0; i < 4; i++) {
        int d = lane + 32 * i;
        float z  = zp[d];
        float yv = c[i] * rn * norm_w[d] * (z / (1.f + expf(-z)));
        __nv_bfloat16 h = __float2bfloat16(yv);
        Yhi[base + d] = h;
        Ylo[base + d] = __float2bfloat16(yv - __bfloat162float(h));
    }
}

// ---------------- launch ----------------
extern "C" void kernel_launch(void* const* d_in, const int* in_sizes, int n_in,
                              void* d_out, int out_size)
{
    const float* hs     = (const float*)d_in[0];
    const float* w_qkvz = (const float*)d_in[1];
    const float* w_ba   = (const float*)d_in[2];
    const float* conv_w = (const float*)d_in[3];
    const float* A_log  = (const float*)d_in[4];
    const float* dt_b   = (const float*)d_in[5];
    const float* norm_w = (const float*)d_in[6];
    const float* w_out  = (const float*)d_in[7];
    float* out = (float*)d_out;

    cudaFuncSetAttribute(gemm_mma_kernel,
                         cudaFuncAttributeMaxDynamicSharedMemorySize, GMM_SMEM);

    void *pv;
    cudaGetSymbolAddress(&pv, g_qkvz);  float* qkvz = (float*)pv;
    cudaGetSymbolAddress(&pv, g_ba);    float* ba   = (float*)pv;
    cudaGetSymbolAddress(&pv, g_q);     float* q    = (float*)pv;
    cudaGetSymbolAddress(&pv, g_k);     float* k    = (float*)pv;
    cudaGetSymbolAddress(&pv, g_v);     float* v    = (float*)pv;
    cudaGetSymbolAddress(&pv, g_decay); float* dec  = (float*)pv;
    cudaGetSymbolAddress(&pv, g_beta);  float* bet  = (float*)pv;
    cudaGetSymbolAddress(&pv, g_core);  float* core = (float*)pv;
    cudaGetSymbolAddress(&pv, g_Ahi);   __nv_bfloat16* Ahi  = (__nv_bfloat16*)pv;
    cudaGetSymbolAddress(&pv, g_Alo);   __nv_bfloat16* Alo  = (__nv_bfloat16*)pv;
    cudaGetSymbolAddress(&pv, g_B1hi);  __nv_bfloat16* B1hi = (__nv_bfloat16*)pv;
    cudaGetSymbolAddress(&pv, g_B1lo);  __nv_bfloat16* B1lo = (__nv_bfloat16*)pv;
    cudaGetSymbolAddress(&pv, g_WOhi);  __nv_bfloat16* WOhi = (__nv_bfloat16*)pv;
    cudaGetSymbolAddress(&pv, g_WOlo);  __nv_bfloat16* WOlo = (__nv_bfloat16*)pv;
    cudaGetSymbolAddress(&pv, g_Yhi);   __nv_bfloat16* Yhi  = (__nv_bfloat16*)pv;
    cudaGetSymbolAddress(&pv, g_Ylo);   __nv_bfloat16* Ylo  = (__nv_bfloat16*)pv;

    // operand prep
    {
        size_t n = (size_t)NTOK * HDIM;
        convert_split_kernel<<<(unsigned)((n / 4 + 255) / 256), 256>>>(hs, Ahi, Alo, n);
    }
    transconv_kernel<<<dim3(QKVZ_COLS / 32, HDIM / 32), 256>>>(w_qkvz, B1hi, B1lo, HDIM, QKVZ_COLS);
    transconv_kernel<<<dim3(HDIM / 32, VAL_DIM / 32), 256>>>(w_out, WOhi, WOlo, VAL_DIM, HDIM);

    // 1) qkvz = hs @ w_qkvz   (tensor cores, 3-pass bf16 split)
    gemm_mma_kernel<<<dim3(NTOK / 128, QKVZ_COLS / 128), 256, GMM_SMEM>>>(
        Ahi, Alo, B1hi, B1lo, qkvz, QKVZ_COLS, HDIM);

    // 2) ba = hs @ w_ba  (fp32)
    sgemm_kernel<<<dim3(1, NTOK / 128), 256>>>(hs, w_ba, ba, NTOK, 64, HDIM);

    // 3) conv + gates
    conv_kernel<<<NTOK, 512>>>(qkvz, ba, conv_w, A_log, dt_b, q, k, v, dec, bet);

    // 4) scan
    scan_kernel<<<BATCH * HV * 2, 256>>>(q, k, v, dec, bet, core);

    // 5) RMSNorm -> y (bf16 split)
    post_kernel<<<NTOK, 1024>>>(core, qkvz, norm_w, Yhi, Ylo);

    // 6) out = y @ w_out  (tensor cores, 3-pass bf16 split)
    gemm_mma_kernel<<<dim3(NTOK / 128, HDIM / 128), 256, GMM_SMEM>>>(
        Yhi, Ylo, WOhi, WOlo, out, HDIM, VAL_DIM);
}